// round 11
// baseline (speedup 1.0000x reference)
#include <cuda_runtime.h>
#include <cuda_bf16.h>

// GraphTrainNN: out[b] = prod_g  w2[g] * (w1[g]^2 + w0[g]*x[b,g]^2) / (w1[g]^2 + x[b,g]^2)
// B = 524288 rows, G = 127 genes. x: (B,G) fp32, w: (G,3) fp32.
//
// R11 = R8 (aligned float4 streaming, low/high split-product assembly, __ldg)
//     + register ping-pong prefetch, WITH NO LAUNCH BOUNDS so ptxas gets a
//       spill-free ~72-reg budget (occ 3 blocks/SM; R4 proved pipelined MLP
//       sustains the DRAM stream at this occupancy, and spills -- not low
//       occupancy -- were what killed R9).
//  - 4-row group = 508 floats = 127 float4; 4 aligned LDG.128 per group,
//    512B contiguous per warp request (minimum sector count).
//  - next group's loads issue BEFORE current group's fold+butterfly, so the
//    ~150-cycle reduction tail always has 2KB in flight per warp.
//  - gene of element (slot,c) = (4*lane + j + c) mod 127 -> 7 param pairs/lane.
//  - lane 31 handles row straddles via split points s={3,2,1,0}; others {4}.
//  - 1 division per row, 5-level butterfly with 4 interleaved chains,
//    float4 output store. prod(w2) hoisted per warp.

#define GG 127

__global__
void hill_f4pp_kernel(const float* __restrict__ x,
                      const float* __restrict__ w,
                      float* __restrict__ out,
                      int ngroups)
{
    const int lane   = threadIdx.x & 31;
    const int warp   = (blockIdx.x * blockDim.x + threadIdx.x) >> 5;
    const int nwarps = (gridDim.x * blockDim.x) >> 5;
    const bool l31   = (lane == 31);

    // ---- per-lane params: genes (4*lane + k) mod 127, k = 0..6 ----
    float p0[7], pn[7];
#pragma unroll
    for (int k = 0; k < 7; ++k) {
        int gene = 4 * lane + k;
        if (gene >= GG) gene -= GG;
        p0[k] = __ldg(&w[gene * 3 + 0]);
        const float kk = __ldg(&w[gene * 3 + 1]);
        pn[k] = kk * kk;
    }
    // prod of w2 over all genes (lane owns genes 4*lane+k, k<4, idx<127)
    float w2l = 1.0f;
#pragma unroll
    for (int k = 0; k < 4; ++k) {
        const int idx = 4 * lane + k;
        if (idx < GG) w2l *= __ldg(&w[idx * 3 + 2]);
    }
#pragma unroll
    for (int o = 16; o; o >>= 1)
        w2l *= __shfl_xor_sync(0xFFFFFFFFu, w2l, o);
    const float W2ALL = w2l;

    const float4* __restrict__ xg = reinterpret_cast<const float4*>(x);

    // ---- load one group's 4 aligned float4 ----
    auto load4 = [&](float4 (&v)[4], int grp) {
        const size_t base = (size_t)grp * GG;    // float4 units
#pragma unroll
        for (int j = 0; j < 4; ++j) {
            int slot = lane + 32 * j;
            if (slot > 126) slot = 126;           // lane31 j=3: dup, discarded
            v[j] = __ldg(xg + base + slot);
        }
    };

    // ---- compute one group (register-light low/high split fold) ----
    auto compute4 = [&](const float4 (&v)[4], int grp) {
        float num[4], den[4];
        float hn = 1.0f, hd = 1.0f;               // carry from previous slot
#pragma unroll
        for (int j = 0; j < 4; ++j) {
            const int s = l31 ? (3 - j) : 4;      // split point for this slot
            float ln = 1.0f, ld = 1.0f;
            float gn = 1.0f, gd = 1.0f;
            const float e[4] = { v[j].x, v[j].y, v[j].z, v[j].w };
#pragma unroll
            for (int c = 0; c < 4; ++c) {
                const int   k  = j + c;
                const float a  = e[c] * e[c];
                const float tn = fmaf(p0[k], a, pn[k]);  // wn + w0*x^2
                const float td = pn[k] + a;              // wn + x^2
                if (c < s) { ln *= tn; ld *= td; }
                else       { gn *= tn; gd *= td; }
            }
            num[j] = hn * ln;
            den[j] = hd * ld;
            hn = gn; hd = gd;
        }

        float rr[4];
#pragma unroll
        for (int r = 0; r < 4; ++r)
            rr[r] = __fdividef(num[r], den[r]);   // <=4 terms: safe fp32 range

#pragma unroll
        for (int o = 1; o <= 16; o <<= 1)
#pragma unroll
            for (int r = 0; r < 4; ++r)
                rr[r] *= __shfl_xor_sync(0xFFFFFFFFu, rr[r], o);

        if (lane == 0) {
            float4 o4;
            o4.x = W2ALL * rr[0];
            o4.y = W2ALL * rr[1];
            o4.z = W2ALL * rr[2];
            o4.w = W2ALL * rr[3];
            *reinterpret_cast<float4*>(out + grp * 4) = o4;
        }
    };

    // ---- pipelined group loop (ping-pong, no copies) ----
    int grp = warp;
    if (grp >= ngroups) return;

    float4 bufA[4], bufB[4];
    load4(bufA, grp);

    for (;;) {
        int nxt = grp + nwarps;
        if (nxt < ngroups) load4(bufB, nxt);      // prefetch while A computes
        compute4(bufA, grp);
        grp = nxt;
        if (grp >= ngroups) break;

        nxt = grp + nwarps;
        if (nxt < ngroups) load4(bufA, nxt);      // prefetch while B computes
        compute4(bufB, grp);
        grp = nxt;
        if (grp >= ngroups) break;
    }
}

extern "C" void kernel_launch(void* const* d_in, const int* in_sizes, int n_in,
                              void* d_out, int out_size)
{
    const float* x = (const float*)d_in[0];   // (B, G) fp32
    const float* w = (const float*)d_in[1];   // (G, 3) fp32
    float* out = (float*)d_out;               // (B, 1) fp32

    const int rows    = in_sizes[0] / GG;     // 524288
    const int ngroups = rows / 4;             // 131072

    const int threads = 256;
    const int blocks  = 2048;                 // 16384 warps -> 8 groups each
    hill_f4pp_kernel<<<blocks, threads>>>(x, w, out, ngroups);
}

// round 12
// speedup vs baseline: 1.1918x; 1.1918x over previous
#include <cuda_runtime.h>
#include <cuda_bf16.h>

// GraphTrainNN: out[b] = prod_g  w2[g] * (w1[g]^2 + w0[g]*x[b,g]^2) / (w1[g]^2 + x[b,g]^2)
// B = 524288 rows, G = 127 genes. x: (B,G) fp32, w: (G,3) fp32.
//
// R12 = R8 (aligned float4 streaming, low/high split-product fold) processing
// TWO independent 4-row groups per iteration, all 8 LDG.128 issued up front.
//  - 4KB in flight per warp per iteration (2x R8) with buffers that live only
//    one iteration: no ping-pong register blow-up (R9/R11 failure mode).
//  - group B's outstanding loads cover group A's fold + butterfly tail.
//  - 4-row group = 127 float4; gene of element (slot,c) = (4*lane+j+c) mod 127
//    -> 7 fixed param pairs/lane; lane 31 split points s={3,2,1,0}.
//  - 1 division per row, 5-level butterfly with 4 interleaved chains,
//    float4 output store per group. prod(w2) hoisted per warp.

#define GG 127

__global__ __launch_bounds__(256, 4)
void hill_f4x2_kernel(const float* __restrict__ x,
                      const float* __restrict__ w,
                      float* __restrict__ out,
                      int ngroups)
{
    const int lane   = threadIdx.x & 31;
    const int warp   = (blockIdx.x * blockDim.x + threadIdx.x) >> 5;
    const int nwarps = (gridDim.x * blockDim.x) >> 5;
    const bool l31   = (lane == 31);

    // ---- per-lane params: genes (4*lane + k) mod 127, k = 0..6 ----
    float p0[7], pn[7];
#pragma unroll
    for (int k = 0; k < 7; ++k) {
        int gene = 4 * lane + k;
        if (gene >= GG) gene -= GG;
        p0[k] = __ldg(&w[gene * 3 + 0]);
        const float kk = __ldg(&w[gene * 3 + 1]);
        pn[k] = kk * kk;
    }
    // prod of w2 over all genes (lane owns genes 4*lane+k, k<4, idx<127)
    float w2l = 1.0f;
#pragma unroll
    for (int k = 0; k < 4; ++k) {
        const int idx = 4 * lane + k;
        if (idx < GG) w2l *= __ldg(&w[idx * 3 + 2]);
    }
#pragma unroll
    for (int o = 16; o; o >>= 1)
        w2l *= __shfl_xor_sync(0xFFFFFFFFu, w2l, o);
    const float W2ALL = w2l;

    const float4* __restrict__ xg = reinterpret_cast<const float4*>(x);

    // slot indices (lane-constant)
    int slot[4];
#pragma unroll
    for (int j = 0; j < 4; ++j) {
        int s = lane + 32 * j;
        if (s > 126) s = 126;                 // lane31 j=3: dup, discarded
        slot[j] = s;
    }

    // ---- fold + reduce one group from its 4 float4 ----
    auto compute4 = [&](const float4 (&v)[4], int grp) {
        float num[4], den[4];
        float hn = 1.0f, hd = 1.0f;           // carry from previous slot
#pragma unroll
        for (int j = 0; j < 4; ++j) {
            const int s = l31 ? (3 - j) : 4;  // split point
            float ln = 1.0f, ld = 1.0f;
            float gn = 1.0f, gd = 1.0f;
            const float e[4] = { v[j].x, v[j].y, v[j].z, v[j].w };
#pragma unroll
            for (int c = 0; c < 4; ++c) {
                const int   k  = j + c;
                const float a  = e[c] * e[c];
                const float tn = fmaf(p0[k], a, pn[k]);  // wn + w0*x^2
                const float td = pn[k] + a;              // wn + x^2
                if (c < s) { ln *= tn; ld *= td; }
                else       { gn *= tn; gd *= td; }
            }
            num[j] = hn * ln;
            den[j] = hd * ld;
            hn = gn; hd = gd;
        }

        float rr[4];
#pragma unroll
        for (int r = 0; r < 4; ++r)
            rr[r] = __fdividef(num[r], den[r]);   // <=4 terms: safe range

#pragma unroll
        for (int o = 1; o <= 16; o <<= 1)
#pragma unroll
            for (int r = 0; r < 4; ++r)
                rr[r] *= __shfl_xor_sync(0xFFFFFFFFu, rr[r], o);

        if (lane == 0) {
            float4 o4;
            o4.x = W2ALL * rr[0];
            o4.y = W2ALL * rr[1];
            o4.z = W2ALL * rr[2];
            o4.w = W2ALL * rr[3];
            *reinterpret_cast<float4*>(out + grp * 4) = o4;
        }
    };

    // ---- main loop: two groups per iteration, loads batched up front ----
    // ngroups = 131072, nwarps = 16384 -> 8 groups per warp -> pairs are safe
    int grpA = warp;
    for (; grpA + nwarps < ngroups; grpA += 2 * nwarps) {
        const int grpB = grpA + nwarps;
        const size_t baseA = (size_t)grpA * GG;
        const size_t baseB = (size_t)grpB * GG;

        float4 vA[4], vB[4];
#pragma unroll
        for (int j = 0; j < 4; ++j) vA[j] = __ldg(xg + baseA + slot[j]);
#pragma unroll
        for (int j = 0; j < 4; ++j) vB[j] = __ldg(xg + baseB + slot[j]);

        compute4(vA, grpA);     // B's loads still in flight here
        compute4(vB, grpB);
    }
    // remainder (odd tail)
    for (; grpA < ngroups; grpA += nwarps) {
        const size_t baseA = (size_t)grpA * GG;
        float4 vA[4];
#pragma unroll
        for (int j = 0; j < 4; ++j) vA[j] = __ldg(xg + baseA + slot[j]);
        compute4(vA, grpA);
    }
}

extern "C" void kernel_launch(void* const* d_in, const int* in_sizes, int n_in,
                              void* d_out, int out_size)
{
    const float* x = (const float*)d_in[0];   // (B, G) fp32
    const float* w = (const float*)d_in[1];   // (G, 3) fp32
    float* out = (float*)d_out;               // (B, 1) fp32

    const int rows    = in_sizes[0] / GG;     // 524288
    const int ngroups = rows / 4;             // 131072

    const int threads = 256;
    const int blocks  = 2048;                 // 16384 warps -> 4 pair-iters
    hill_f4x2_kernel<<<blocks, threads>>>(x, w, out, ngroups);
}

// round 13
// speedup vs baseline: 1.2258x; 1.0285x over previous
#include <cuda_runtime.h>
#include <cuda_bf16.h>

// GraphTrainNN: out[b] = prod_g  w2[g] * (w1[g]^2 + w0[g]*x[b,g]^2) / (w1[g]^2 + x[b,g]^2)
// B = 524288 rows, G = 127 genes. x: (B,G) fp32, w: (G,3) fp32.
//
// R13 = R8 (best measured: 44.86us kernel, DRAM 76.5%) with finer block
// granularity: 128-thread blocks, launch_bounds(128,10) -> same 48-reg
// allocation and 40 warps/SM, but 4096 blocks give the work-stealing
// scheduler a smaller balancing quantum across waves.
//  - 4-row group = 508 floats = 127 float4; warp loads slots lane+32j ->
//    4 aligned LDG.128, 512B contiguous per request (minimum sectors).
//  - gene of element (slot,c) = (4*lane + j + c) mod 127 [128 == 1 mod 127]
//    -> 7 fixed (w0, w1^2) pairs per lane.
//  - lane 31 handles row straddles via low/high split points s={3,2,1,0};
//    all other lanes s=4 (everything low). Uniform fold num[r]=high[r-1]*low[r].
//  - 1 fast division per row (<=4-term operands: safe fp32 range),
//    5-level butterfly with 4 interleaved chains, float4 output store.
//  - prod(w2) over all genes hoisted to a per-warp constant.

#define GG 127

__global__ __launch_bounds__(128, 10)
void hill_f4_final_kernel(const float* __restrict__ x,
                          const float* __restrict__ w,
                          float* __restrict__ out,
                          int ngroups)
{
    const int lane   = threadIdx.x & 31;
    const int warp   = (blockIdx.x * blockDim.x + threadIdx.x) >> 5;
    const int nwarps = (gridDim.x * blockDim.x) >> 5;
    const bool l31   = (lane == 31);

    // ---- per-lane params: genes (4*lane + k) mod 127, k = 0..6 ----
    float p0[7], pn[7];
#pragma unroll
    for (int k = 0; k < 7; ++k) {
        int gene = 4 * lane + k;
        if (gene >= GG) gene -= GG;
        p0[k] = __ldg(&w[gene * 3 + 0]);
        const float kk = __ldg(&w[gene * 3 + 1]);
        pn[k] = kk * kk;
    }
    // prod of w2 over all genes (lane owns genes 4*lane+k, k<4, idx<127)
    float w2l = 1.0f;
#pragma unroll
    for (int k = 0; k < 4; ++k) {
        const int idx = 4 * lane + k;
        if (idx < GG) w2l *= __ldg(&w[idx * 3 + 2]);
    }
#pragma unroll
    for (int o = 16; o; o >>= 1)
        w2l *= __shfl_xor_sync(0xFFFFFFFFu, w2l, o);
    const float W2ALL = w2l;

    const float4* __restrict__ xg = reinterpret_cast<const float4*>(x);

    for (int grp = warp; grp < ngroups; grp += nwarps) {
        // ---- 4 aligned vector loads (independent, issued up front) ----
        float4 v[4];
        const size_t base = (size_t)grp * GG;   // float4 units
#pragma unroll
        for (int j = 0; j < 4; ++j) {
            int slot = lane + 32 * j;
            if (slot > 126) slot = 126;          // lane31 j=3: dup, discarded
            v[j] = __ldg(xg + base + slot);
        }

        // ---- low/high split products per slot, folded across rows ----
        float num[4], den[4];
        float hn = 1.0f, hd = 1.0f;              // carry from previous slot
#pragma unroll
        for (int j = 0; j < 4; ++j) {
            const int s = l31 ? (3 - j) : 4;     // split point for this slot
            float ln = 1.0f, ld = 1.0f;          // low part (this row)
            float gn = 1.0f, gd = 1.0f;          // high part (next row)
            const float e[4] = { v[j].x, v[j].y, v[j].z, v[j].w };
#pragma unroll
            for (int c = 0; c < 4; ++c) {
                const int   k  = j + c;
                const float a  = e[c] * e[c];
                const float tn = fmaf(p0[k], a, pn[k]);  // wn + w0*x^2
                const float td = pn[k] + a;              // wn + x^2
                if (c < s) { ln *= tn; ld *= td; }
                else       { gn *= tn; gd *= td; }
            }
            num[j] = hn * ln;
            den[j] = hd * ld;
            hn = gn; hd = gd;
        }

        // ---- 1 division per row ----
        float rr[4];
#pragma unroll
        for (int r = 0; r < 4; ++r)
            rr[r] = __fdividef(num[r], den[r]);

        // ---- 32-lane product, 4 independent chains interleaved ----
#pragma unroll
        for (int o = 1; o <= 16; o <<= 1)
#pragma unroll
            for (int r = 0; r < 4; ++r)
                rr[r] *= __shfl_xor_sync(0xFFFFFFFFu, rr[r], o);

        if (lane == 0) {
            float4 o4;
            o4.x = W2ALL * rr[0];
            o4.y = W2ALL * rr[1];
            o4.z = W2ALL * rr[2];
            o4.w = W2ALL * rr[3];
            *reinterpret_cast<float4*>(out + grp * 4) = o4;
        }
    }
}

extern "C" void kernel_launch(void* const* d_in, const int* in_sizes, int n_in,
                              void* d_out, int out_size)
{
    const float* x = (const float*)d_in[0];   // (B, G) fp32
    const float* w = (const float*)d_in[1];   // (G, 3) fp32
    float* out = (float*)d_out;               // (B, 1) fp32

    const int rows    = in_sizes[0] / GG;     // 524288
    const int ngroups = rows / 4;             // 131072

    const int threads = 128;
    const int blocks  = 4096;                 // 16384 warps -> 8 groups each
    hill_f4_final_kernel<<<blocks, threads>>>(x, w, out, ngroups);
}

// round 14
// speedup vs baseline: 1.2697x; 1.0358x over previous
#include <cuda_runtime.h>
#include <cuda_bf16.h>

// GraphTrainNN: out[b] = prod_g  w2[g] * (w1[g]^2 + w0[g]*x[b,g]^2) / (w1[g]^2 + x[b,g]^2)
// B = 524288 rows, G = 127 genes. x: (B,G) fp32, w: (G,3) fp32.
//
// R14 = R8 body (best measured: 48 regs, aligned float4 streaming, low/high
// split-product fold) + SINGLE-WAVE PERSISTENT GRID.
//  - 740 blocks = 148 SMs x 5 resident -> exactly one wave, no wave
//    quantization (2048 equal-work blocks ran 2.77 lock-step waves with the
//    last wave 77% full). Grid-stride: each warp does 22-23 groups.
//  - 4-row group = 508 floats = 127 float4; warp loads slots lane+32j ->
//    4 aligned LDG.128, 512B contiguous per request (minimum sectors).
//  - gene of element (slot,c) = (4*lane + j + c) mod 127 [128 == 1 mod 127]
//    -> 7 fixed (w0, w1^2) pairs per lane.
//  - lane 31 handles row straddles via split points s={3,2,1,0}; others s=4.
//  - 1 fast division per row, 5-level butterfly with 4 interleaved chains,
//    float4 output store. prod(w2) hoisted per warp.

#define GG 127
#define NBLOCKS 740   // 148 SMs x 5 resident blocks: exactly one wave

__global__ __launch_bounds__(256, 5)
void hill_f4w_kernel(const float* __restrict__ x,
                     const float* __restrict__ w,
                     float* __restrict__ out,
                     int ngroups)
{
    const int lane   = threadIdx.x & 31;
    const int warp   = (blockIdx.x * blockDim.x + threadIdx.x) >> 5;
    const int nwarps = (gridDim.x * blockDim.x) >> 5;
    const bool l31   = (lane == 31);

    // ---- per-lane params: genes (4*lane + k) mod 127, k = 0..6 ----
    float p0[7], pn[7];
#pragma unroll
    for (int k = 0; k < 7; ++k) {
        int gene = 4 * lane + k;
        if (gene >= GG) gene -= GG;
        p0[k] = __ldg(&w[gene * 3 + 0]);
        const float kk = __ldg(&w[gene * 3 + 1]);
        pn[k] = kk * kk;
    }
    // prod of w2 over all genes (lane owns genes 4*lane+k, k<4, idx<127)
    float w2l = 1.0f;
#pragma unroll
    for (int k = 0; k < 4; ++k) {
        const int idx = 4 * lane + k;
        if (idx < GG) w2l *= __ldg(&w[idx * 3 + 2]);
    }
#pragma unroll
    for (int o = 16; o; o >>= 1)
        w2l *= __shfl_xor_sync(0xFFFFFFFFu, w2l, o);
    const float W2ALL = w2l;

    const float4* __restrict__ xg = reinterpret_cast<const float4*>(x);

    for (int grp = warp; grp < ngroups; grp += nwarps) {
        // ---- 4 aligned vector loads (independent, issued up front) ----
        float4 v[4];
        const size_t base = (size_t)grp * GG;   // float4 units
#pragma unroll
        for (int j = 0; j < 4; ++j) {
            int slot = lane + 32 * j;
            if (slot > 126) slot = 126;          // lane31 j=3: dup, discarded
            v[j] = __ldg(xg + base + slot);
        }

        // ---- low/high split products per slot, folded across rows ----
        float num[4], den[4];
        float hn = 1.0f, hd = 1.0f;              // carry from previous slot
#pragma unroll
        for (int j = 0; j < 4; ++j) {
            const int s = l31 ? (3 - j) : 4;     // split point for this slot
            float ln = 1.0f, ld = 1.0f;          // low part (this row)
            float gn = 1.0f, gd = 1.0f;          // high part (next row)
            const float e[4] = { v[j].x, v[j].y, v[j].z, v[j].w };
#pragma unroll
            for (int c = 0; c < 4; ++c) {
                const int   k  = j + c;
                const float a  = e[c] * e[c];
                const float tn = fmaf(p0[k], a, pn[k]);  // wn + w0*x^2
                const float td = pn[k] + a;              // wn + x^2
                if (c < s) { ln *= tn; ld *= td; }
                else       { gn *= tn; gd *= td; }
            }
            num[j] = hn * ln;
            den[j] = hd * ld;
            hn = gn; hd = gd;
        }

        // ---- 1 division per row (<=4-term operands: safe fp32 range) ----
        float rr[4];
#pragma unroll
        for (int r = 0; r < 4; ++r)
            rr[r] = __fdividef(num[r], den[r]);

        // ---- 32-lane product, 4 independent chains interleaved ----
#pragma unroll
        for (int o = 1; o <= 16; o <<= 1)
#pragma unroll
            for (int r = 0; r < 4; ++r)
                rr[r] *= __shfl_xor_sync(0xFFFFFFFFu, rr[r], o);

        if (lane == 0) {
            float4 o4;
            o4.x = W2ALL * rr[0];
            o4.y = W2ALL * rr[1];
            o4.z = W2ALL * rr[2];
            o4.w = W2ALL * rr[3];
            *reinterpret_cast<float4*>(out + grp * 4) = o4;
        }
    }
}

extern "C" void kernel_launch(void* const* d_in, const int* in_sizes, int n_in,
                              void* d_out, int out_size)
{
    const float* x = (const float*)d_in[0];   // (B, G) fp32
    const float* w = (const float*)d_in[1];   // (G, 3) fp32
    float* out = (float*)d_out;               // (B, 1) fp32

    const int rows    = in_sizes[0] / GG;     // 524288
    const int ngroups = rows / 4;             // 131072

    hill_f4w_kernel<<<NBLOCKS, 256>>>(x, w, out, ngroups);
}